// round 4
// baseline (speedup 1.0000x reference)
#include <cuda_runtime.h>

// Problem constants
#define BATCH 8
#define CH    128
#define MIDC  64
#define OUTC  128
#define TT    4
#define NNN   512
#define TN    2048   // T*N

// ---------------------------------------------------------------------------
// Scratch (device globals -- allocation-free per harness rules)
// ---------------------------------------------------------------------------
__device__ float g_theta [BATCH * TN * MIDC];            // [b][q][m]
__device__ float g_phi   [BATCH * MIDC * TN];            // [b][m][k]
__device__ float g_g     [BATCH * TN * MIDC];            // [b][k][m]
__device__ float g_gs    [BATCH * TN * MIDC];            // g scaled by 1/Z[k]
__device__ float g_scores[BATCH * TN * TN];              // [b][q][k]  (128 MB)
__device__ float g_Zp    [4 * BATCH * TN];               // partial column sums
__device__ float g_invZ  [BATCH * TN];
__device__ float g_y4    [4 * BATCH * TN * MIDC];        // split-K partials
__device__ float g_y     [BATCH * TN * MIDC];            // [b][q][m]
__device__ float g_ref   [BATCH * TN * OUTC];            // [b][q][o]

// ---------------------------------------------------------------------------
// Fast exp: FFMA/ALU only (avoids the MUFU 0.5/cyc/SM throughput trap).
// exp(x) = 2^(x*log2e); round-to-int via magic constant, degree-5 Taylor for
// 2^f on f in [-0.5, 0.5] (rel err ~2.4e-6), exponent via bit assembly.
// Valid here since scores s >= 0 and s <~ 15.
// ---------------------------------------------------------------------------
__device__ __forceinline__ float fexp(float x) {
    const float L2E = 1.4426950408889634f;
    float z = fmaf(x, L2E, 12582912.0f);          // 1.5*2^23: rounds to int
    float n = z - 12582912.0f;                    // integer part as float
    float f = fmaf(x, L2E, -n);                   // frac in [-0.5, 0.5]
    float p =              1.3333558146e-3f;      // ln2^5/120
    p = fmaf(p, f,         9.6181291076e-3f);     // ln2^4/24
    p = fmaf(p, f,         5.5504108665e-2f);     // ln2^3/6
    p = fmaf(p, f,         2.4022650696e-1f);     // ln2^2/2
    p = fmaf(p, f,         6.9314718056e-1f);     // ln2
    p = fmaf(p, f,         1.0f);
    int ni = __float_as_int(z) - 0x4B400000;      // n as integer
    float scale = __int_as_float((ni + 127) << 23);
    return p * scale;
}

// ---------------------------------------------------------------------------
// Generic fp32 tiled GEMM:  C[M,N] = op( A[M,K] * B[K,N] + bias )
//   TRANSB: B supplied as [N,K] row-major (ldb = K stride)
//   BIAS_MODE: 0 none, 1 per-row(M), 2 per-col(N);  RELU; TRANSC: store C^T
// ---------------------------------------------------------------------------
template<int BM, int BN, int BK, int TM, int TNr, bool TRANSB,
         int BIAS_MODE, bool RELU, bool TRANSC>
__global__ void __launch_bounds__((BM/TM)*(BN/TNr))
gemm_f32(const float* __restrict__ A, const float* __restrict__ B,
         const float* __restrict__ bias, float* __restrict__ C,
         int lda, int ldb, int ldc, int K,
         int strideA, int strideB, int strideC)
{
    constexpr int THREADS = (BM/TM) * (BN/TNr);
    __shared__ float As[BM][BK + 1];
    __shared__ float Bs[BK][BN + 4];

    const int b = blockIdx.z;
    A += (size_t)b * strideA;
    B += (size_t)b * strideB;
    C += (size_t)b * strideC;

    const int n0 = blockIdx.x * BN;
    const int m0 = blockIdx.y * BM;
    const int tid = threadIdx.x;
    const int tx = tid % (BN / TNr);
    const int ty = tid / (BN / TNr);

    float acc[TM][TNr];
#pragma unroll
    for (int i = 0; i < TM; i++)
#pragma unroll
        for (int j = 0; j < TNr; j++) acc[i][j] = 0.f;

    for (int kt = 0; kt < K; kt += BK) {
#pragma unroll 4
        for (int r = tid; r < BM * BK; r += THREADS) {
            int ar = r / BK, ac = r % BK;
            As[ar][ac] = A[(m0 + ar) * lda + kt + ac];
        }
        if (!TRANSB) {
#pragma unroll 4
            for (int r = tid; r < BK * BN; r += THREADS) {
                int br = r / BN, bc = r % BN;
                Bs[br][bc] = B[(kt + br) * ldb + n0 + bc];
            }
        } else {
#pragma unroll 4
            for (int r = tid; r < BK * BN; r += THREADS) {
                int bn = r / BK, bk = r % BK;
                Bs[bk][bn] = B[(n0 + bn) * ldb + kt + bk];
            }
        }
        __syncthreads();
#pragma unroll
        for (int kk = 0; kk < BK; kk++) {
            float a[TM], bv[TNr];
#pragma unroll
            for (int i = 0; i < TM; i++) a[i] = As[ty * TM + i][kk];
#pragma unroll
            for (int j = 0; j < TNr; j++) bv[j] = Bs[kk][tx * TNr + j];
#pragma unroll
            for (int i = 0; i < TM; i++)
#pragma unroll
                for (int j = 0; j < TNr; j++)
                    acc[i][j] = fmaf(a[i], bv[j], acc[i][j]);
        }
        __syncthreads();
    }

#pragma unroll
    for (int i = 0; i < TM; i++) {
        int m = m0 + ty * TM + i;
#pragma unroll
        for (int j = 0; j < TNr; j++) {
            int n = n0 + tx * TNr + j;
            float v = acc[i][j];
            if (BIAS_MODE == 1) v += bias[m];
            if (BIAS_MODE == 2) v += bias[n];
            if (RELU) v = fmaxf(v, 0.f);
            if (!TRANSC) C[m * ldc + n] = v;
            else         C[n * ldc + m] = v;
        }
    }
}

// ---------------------------------------------------------------------------
// Column sums of exp(scores) over q (softmax is over the QUERY axis).
// grid (ktile=8, qchunk=4, batch=8), 256 thr. Deterministic partials.
// ---------------------------------------------------------------------------
__global__ void __launch_bounds__(256)
colsum_kernel(const float* __restrict__ S, float* __restrict__ Zp)
{
    const int kt = blockIdx.x, qc = blockIdx.y, b = blockIdx.z;
    const int k = kt * 256 + threadIdx.x;
    const float* Sb = S + (size_t)b * TN * TN;
    const int q0 = qc * 512;
    float a0 = 0.f, a1 = 0.f, a2 = 0.f, a3 = 0.f;
#pragma unroll 2
    for (int q = q0; q < q0 + 512; q += 4) {
        a0 += fexp(Sb[(q + 0) * TN + k]);
        a1 += fexp(Sb[(q + 1) * TN + k]);
        a2 += fexp(Sb[(q + 2) * TN + k]);
        a3 += fexp(Sb[(q + 3) * TN + k]);
    }
    Zp[(qc * BATCH + b) * TN + k] = (a0 + a1) + (a2 + a3);
}

__global__ void __launch_bounds__(256)
invz_kernel(const float* __restrict__ Zp, float* __restrict__ invZ)
{
    int idx = blockIdx.x * 256 + threadIdx.x;   // 16384
    float z = (Zp[idx] + Zp[16384 + idx]) + (Zp[32768 + idx] + Zp[49152 + idx]);
    invZ[idx] = 1.0f / z;
}

__global__ void __launch_bounds__(256)
scale_g_kernel(const float* __restrict__ G, const float* __restrict__ invZ,
               float* __restrict__ Gs)
{
    int idx = blockIdx.x * 256 + threadIdx.x;   // 1048576; layout [b][k][m]
    Gs[idx] = G[idx] * invZ[idx >> 6];
}

// ---------------------------------------------------------------------------
// y[q][m] = sum_k exp(s[q][k]) * gs[k][m]    (gs pre-scaled by 1/Z[k])
// grid (split=4, qtile=8, batch=8), 256 thr, TM=TN=8.
// ---------------------------------------------------------------------------
__global__ void __launch_bounds__(256)
attn_y_kernel(const float* __restrict__ S, const float* __restrict__ Gs,
              float* __restrict__ Y4)
{
    constexpr int BM = 256, BN = 64, BK = 32, TM = 8, TNr = 8;
    constexpr int THREADS = 256;
    __shared__ float As[BM][BK + 1];
    __shared__ float Bs[BK][BN + 4];

    const int sp = blockIdx.x, qt = blockIdx.y, b = blockIdx.z;
    const float* Sb = S  + (size_t)b * TN * TN;
    const float* Gb = Gs + (size_t)b * TN * MIDC;
    const int m0 = qt * BM;
    const int kbeg = sp * (TN / 4), kend = kbeg + (TN / 4);
    const int tid = threadIdx.x;
    const int tx = tid % (BN / TNr);   // 0..7
    const int ty = tid / (BN / TNr);   // 0..31

    float acc[TM][TNr];
#pragma unroll
    for (int i = 0; i < TM; i++)
#pragma unroll
        for (int j = 0; j < TNr; j++) acc[i][j] = 0.f;

    for (int kt = kbeg; kt < kend; kt += BK) {
#pragma unroll 8
        for (int r = tid; r < BM * BK; r += THREADS) {
            int ar = r / BK, ac = r % BK;
            As[ar][ac] = fexp(Sb[(m0 + ar) * TN + kt + ac]);
        }
#pragma unroll 4
        for (int r = tid; r < BK * BN; r += THREADS) {
            int br = r / BN, bc = r % BN;
            Bs[br][bc] = Gb[(kt + br) * MIDC + bc];
        }
        __syncthreads();
#pragma unroll
        for (int kk = 0; kk < BK; kk++) {
            float a[TM], bv[TNr];
#pragma unroll
            for (int i = 0; i < TM; i++) a[i] = As[ty * TM + i][kk];
#pragma unroll
            for (int j = 0; j < TNr; j++) bv[j] = Bs[kk][tx * TNr + j];
#pragma unroll
            for (int i = 0; i < TM; i++)
#pragma unroll
                for (int j = 0; j < TNr; j++)
                    acc[i][j] = fmaf(a[i], bv[j], acc[i][j]);
        }
        __syncthreads();
    }

    float* Yo = Y4 + (size_t)sp * (BATCH * TN * MIDC) + (size_t)b * TN * MIDC;
#pragma unroll
    for (int i = 0; i < TM; i++) {
        int q = m0 + ty * TM + i;
#pragma unroll
        for (int j = 0; j < TNr; j++)
            Yo[q * MIDC + tx * TNr + j] = acc[i][j];
    }
}

__global__ void __launch_bounds__(256)
reduce_y_kernel(const float* __restrict__ Y4, float* __restrict__ Y)
{
    int idx = blockIdx.x * 256 + threadIdx.x;   // 1048576
    Y[idx] = (Y4[idx] + Y4[1048576 + idx]) + (Y4[2097152 + idx] + Y4[3145728 + idx]);
}

// ---------------------------------------------------------------------------
// Final scatter: out[b,c,t,n] = refined[b, q, o] + pc[b,c,t,n]
// flat = t*65536 + n*128 + c ; o = flat>>11 ; q = flat&2047
//   => q = (n&15)*128 + c ; o = t*32 + (n>>4)
// Total elements: BATCH*CH*TT*NNN = 2097152  (8192 blocks x 256 threads)
// ---------------------------------------------------------------------------
__global__ void __launch_bounds__(256)
scatter_kernel(const float* __restrict__ R, const float* __restrict__ pc,
               float* __restrict__ out)
{
    int idx = blockIdx.x * 256 + threadIdx.x;   // 2097152
    int b = idx >> 18;                          // 262144 = CH*TN per batch
    int r = idx & 262143;                       // c*2048 + t*512 + n
    int c = r >> 11;
    int t = (r >> 9) & 3;
    int n = r & 511;
    int q = ((n & 15) << 7) + c;
    int o = (t << 5) + (n >> 4);
    out[idx] = R[(((b << 11) + q) << 7) + o] + pc[idx];
}

// ---------------------------------------------------------------------------
// Host launcher (graph-capturable: kernel launches on default stream only)
// ---------------------------------------------------------------------------
extern "C" void kernel_launch(void* const* d_in, const int* in_sizes, int n_in,
                              void* d_out, int out_size)
{
    const float* pc = (const float*)d_in[0];
    const float* tw = (const float*)d_in[1];
    const float* tb = (const float*)d_in[2];
    const float* pw = (const float*)d_in[3];
    const float* pb = (const float*)d_in[4];
    const float* gw = (const float*)d_in[5];
    const float* gb = (const float*)d_in[6];
    const float* rw = (const float*)d_in[7];
    const float* rb = (const float*)d_in[8];
    float* out = (float*)d_out;

    float *theta, *phi, *gg, *gs, *scores, *Zp, *invZ, *y4, *y, *ref;
    cudaGetSymbolAddress((void**)&theta,  g_theta);
    cudaGetSymbolAddress((void**)&phi,    g_phi);
    cudaGetSymbolAddress((void**)&gg,     g_g);
    cudaGetSymbolAddress((void**)&gs,     g_gs);
    cudaGetSymbolAddress((void**)&scores, g_scores);
    cudaGetSymbolAddress((void**)&Zp,     g_Zp);
    cudaGetSymbolAddress((void**)&invZ,   g_invZ);
    cudaGetSymbolAddress((void**)&y4,     g_y4);
    cudaGetSymbolAddress((void**)&y,      g_y);
    cudaGetSymbolAddress((void**)&ref,    g_ref);

    const int sPC  = CH * TN;        // 262144  per-batch pc stride
    const int sPRJ = MIDC * TN;      // 131072  per-batch projection stride
    const int sSC  = TN * TN;        // 4194304 per-batch scores stride
    const int sRF  = TN * OUTC;      // 262144  per-batch refined stride

    // 1) Projections: [64 x 2048] = W[64x128] * pc[128x2048], +bias(row), relu
    dim3 gP(TN / 128, 1, BATCH);
    gemm_f32<64,128,32,4,8,false,1,true,true ><<<gP, 256>>>(tw, pc, tb, theta,
        CH, TN, MIDC, CH, 0, sPC, sPRJ);
    gemm_f32<64,128,32,4,8,false,1,true,false><<<gP, 256>>>(pw, pc, pb, phi,
        CH, TN, TN,   CH, 0, sPC, sPRJ);
    gemm_f32<64,128,32,4,8,false,1,true,true ><<<gP, 256>>>(gw, pc, gb, gg,
        CH, TN, MIDC, CH, 0, sPC, sPRJ);

    // 2) scores[q][k] = theta[q][m] * phi[m][k]   (2048x2048, K=64, x8)
    dim3 gS(TN / 128, TN / 128, BATCH);
    gemm_f32<128,128,32,8,8,false,0,false,false><<<gS, 256>>>(theta, phi,
        (const float*)0, scores, MIDC, TN, TN, MIDC, sPRJ, sPRJ, sSC);

    // 3) Softmax denominators over the query axis
    colsum_kernel <<<dim3(8, 4, BATCH), 256>>>(scores, Zp);
    invz_kernel   <<<64, 256>>>(Zp, invZ);
    scale_g_kernel<<<4096, 256>>>(gg, invZ, gs);

    // 4) y = exp(scores) * gs   (split-K=4, deterministic partials)
    attn_y_kernel <<<dim3(4, TN / 256, BATCH), 256>>>(scores, gs, y4);
    reduce_y_kernel<<<4096, 256>>>(y4, y);

    // 5) refined[q][o] = relu( y[q][m] * rw[o][m]^T + rb[o] )
    dim3 gR(OUTC / 128, TN / 128, BATCH);
    gemm_f32<128,128,32,8,8,true,2,true,false><<<gR, 256>>>(y, rw, rb, ref,
        MIDC, MIDC, OUTC, MIDC, sPRJ, 0, sRF);

    // 6) permuted reshape + residual  (2097152 elements)
    scatter_kernel<<<8192, 256>>>(ref, pc, out);
}

// round 5
// speedup vs baseline: 1.7313x; 1.7313x over previous
#include <cuda_runtime.h>

#define BATCH 8
#define CH    128
#define MIDC  64
#define OUTC  128
#define TN    2048

typedef unsigned long long u64;
typedef unsigned int u32;

// ---------------------------------------------------------------------------
// Scratch (device globals; allocation-free per harness rules)
// ---------------------------------------------------------------------------
__device__ float g_theta[BATCH * MIDC * TN];   // [b][m][q]  (k-major for GEMM)
__device__ float g_phi  [BATCH * MIDC * TN];   // [b][m][k]
__device__ float g_g    [BATCH * TN * MIDC];   // [b][k][m]  (scaled in place)
__device__ float g_ET   [BATCH * TN * TN];     // [b][k][q] = exp(scores)^T
__device__ float g_Zp   [16 * BATCH * TN];     // per-qtile column-sum partials
__device__ float g_invZ [BATCH * TN];
__device__ float g_y4   [4 * BATCH * MIDC * TN]; // split-K partials of y^T
__device__ float g_ref  [BATCH * TN * OUTC];   // [b][q][o]

// ---------------------------------------------------------------------------
// Packed fp32x2 primitives (FFMA2 etc. are PTX-only; ptxas never emits them
// from plain C++ -- see sm_103a notes). These double fp32 FMA throughput.
// ---------------------------------------------------------------------------
__device__ __forceinline__ u64 pk2(float a, float b) {
    u64 r; asm("mov.b64 %0,{%1,%2};" : "=l"(r) : "f"(a), "f"(b)); return r;
}
__device__ __forceinline__ void upk2(u64 p, float& a, float& b) {
    asm("mov.b64 {%0,%1},%2;" : "=f"(a), "=f"(b) : "l"(p));
}
__device__ __forceinline__ u64 splat2(float x) {
    u64 r; asm("mov.b64 %0,{%1,%1};" : "=l"(r) : "f"(x)); return r;
}
__device__ __forceinline__ u64 fma2_(u64 a, u64 b, u64 c) {
    u64 d; asm("fma.rn.f32x2 %0,%1,%2,%3;" : "=l"(d) : "l"(a), "l"(b), "l"(c)); return d;
}
__device__ __forceinline__ u64 add2_(u64 a, u64 b) {
    u64 d; asm("add.rn.f32x2 %0,%1,%2;" : "=l"(d) : "l"(a), "l"(b)); return d;
}
__device__ __forceinline__ u64 mul2_(u64 a, u64 b) {
    u64 d; asm("mul.rn.f32x2 %0,%1,%2;" : "=l"(d) : "l"(a), "l"(b)); return d;
}

// Packed fast exp (valid for x >= 0 here; scores are products of ReLU outputs).
// exp(x)=2^(x*log2e): magic-number round + deg-5 poly, all on the f32x2 pipe;
// exponent assembly on the ALU pipe. rel err ~3e-6.
__device__ __forceinline__ u64 fexp2v(u64 x) {
    const float L2E = 1.4426950408889634f;
    u64 t = mul2_(x, pk2(L2E, L2E));
    u64 z = add2_(t, pk2(12582912.0f, 12582912.0f));
    u64 n = add2_(z, pk2(-12582912.0f, -12582912.0f));
    u64 f = add2_(t, n ^ 0x8000000080000000ULL);        // t - n
    u64 p =                 pk2(1.3333558146e-3f, 1.3333558146e-3f);
    p = fma2_(p, f,         pk2(9.6181291076e-3f, 9.6181291076e-3f));
    p = fma2_(p, f,         pk2(5.5504108665e-2f, 5.5504108665e-2f));
    p = fma2_(p, f,         pk2(2.4022650696e-1f, 2.4022650696e-1f));
    p = fma2_(p, f,         pk2(6.9314718056e-1f, 6.9314718056e-1f));
    p = fma2_(p, f,         pk2(1.0f, 1.0f));
    u32 zl = (u32)z, zh = (u32)(z >> 32);
    u32 sl = (zl + 0xB4C0007Fu) << 23;                  // (zbits-0x4B400000+127)<<23
    u32 sh = (zh + 0xB4C0007Fu) << 23;
    return mul2_(p, ((u64)sh << 32) | sl);
}

// ---------------------------------------------------------------------------
// 1) Fused projections (theta/phi/g in one launch, blockIdx.y selects).
//    out = relu(W[64x128] * pc[128x2048] + b).  theta,phi -> [m][tn]; g -> [tn][m].
// ---------------------------------------------------------------------------
__global__ void __launch_bounds__(256)
proj_kernel(const float* __restrict__ pc,
            const float* __restrict__ tw, const float* __restrict__ tb,
            const float* __restrict__ pw, const float* __restrict__ pb,
            const float* __restrict__ gw, const float* __restrict__ gb,
            float* __restrict__ theta, float* __restrict__ phi, float* __restrict__ g)
{
    __shared__ float As[32 * 64];    // W^T chunk [cc][m]
    __shared__ float Bs[32 * 128];   // pc chunk  [cc][tn]
    const int b = blockIdx.z, pj = blockIdx.y;
    const int n0 = blockIdx.x * 128;
    const float *W, *bi; float* out;
    if (pj == 0)      { W = tw; bi = tb; out = theta; }
    else if (pj == 1) { W = pw; bi = pb; out = phi;   }
    else              { W = gw; bi = gb; out = g;     }
    const float* pcb = pc + (size_t)b * CH * TN;
    const int tid = threadIdx.x;
    const int tx = tid & 15, ty = tid >> 4;      // tx: tn-oct, ty: mid-quad

    u64 acc[4][4];
#pragma unroll
    for (int i = 0; i < 4; i++)
#pragma unroll
        for (int j = 0; j < 4; j++) acc[i][j] = 0ULL;

    for (int ct = 0; ct < 128; ct += 32) {
#pragma unroll
        for (int t = 0; t < 2; t++) {            // W^T: 2048 elems
            int f4 = tid + t * 256;              // 0..511
            int m = f4 >> 3, c4 = (f4 & 7) << 2;
            float4 w4 = *(const float4*)&W[m * 128 + ct + c4];
            As[(c4 + 0) * 64 + m] = w4.x;
            As[(c4 + 1) * 64 + m] = w4.y;
            As[(c4 + 2) * 64 + m] = w4.z;
            As[(c4 + 3) * 64 + m] = w4.w;
        }
#pragma unroll
        for (int t = 0; t < 4; t++) {            // pc: 4096 floats
            int f4 = tid + t * 256;              // 0..1023
            int cc = f4 >> 5, c4 = (f4 & 31) << 2;
            *(float4*)&Bs[cc * 128 + c4] =
                *(const float4*)&pcb[(size_t)(ct + cc) * TN + n0 + c4];
        }
        __syncthreads();
#pragma unroll 8
        for (int cc = 0; cc < 32; cc++) {
            float4 av = *(float4*)&As[cc * 64 + ty * 4];
            ulonglong2 b01 = *(ulonglong2*)&Bs[cc * 128 + tx * 8];
            ulonglong2 b23 = *(ulonglong2*)&Bs[cc * 128 + tx * 8 + 4];
            u64 aa[4] = { splat2(av.x), splat2(av.y), splat2(av.z), splat2(av.w) };
            u64 bb[4] = { b01.x, b01.y, b23.x, b23.y };
#pragma unroll
            for (int i = 0; i < 4; i++)
#pragma unroll
                for (int j = 0; j < 4; j++)
                    acc[i][j] = fma2_(aa[i], bb[j], acc[i][j]);
        }
        __syncthreads();
    }

    float v[4][8];
#pragma unroll
    for (int i = 0; i < 4; i++) {
#pragma unroll
        for (int j2 = 0; j2 < 4; j2++) upk2(acc[i][j2], v[i][2 * j2], v[i][2 * j2 + 1]);
        float bv = bi[ty * 4 + i];
#pragma unroll
        for (int j = 0; j < 8; j++) v[i][j] = fmaxf(v[i][j] + bv, 0.f);
    }
    if (pj < 2) {                                // [m][tn]
        float* ob = out + (size_t)b * MIDC * TN;
#pragma unroll
        for (int i = 0; i < 4; i++) {
            size_t row = (size_t)(ty * 4 + i) * TN + n0 + tx * 8;
            *(float4*)&ob[row]     = make_float4(v[i][0], v[i][1], v[i][2], v[i][3]);
            *(float4*)&ob[row + 4] = make_float4(v[i][4], v[i][5], v[i][6], v[i][7]);
        }
    } else {                                     // g: [tn][m]
        float* ob = out + (size_t)b * TN * MIDC;
#pragma unroll
        for (int j = 0; j < 8; j++)
            *(float4*)&ob[(size_t)(n0 + tx * 8 + j) * MIDC + ty * 4] =
                make_float4(v[0][j], v[1][j], v[2][j], v[3][j]);
    }
}

// ---------------------------------------------------------------------------
// 2) scores + exp + column-sum partials, storing E^T[k][q].
//    s[q][k] = sum_m theta[m][q] * phi[m][k]  (both operands m-major, K=64)
// ---------------------------------------------------------------------------
__global__ void __launch_bounds__(256)
scores_kernel(const float* __restrict__ TH, const float* __restrict__ PH,
              float* __restrict__ ET, float* __restrict__ Zp)
{
    __shared__ float sm[8192];                   // As[32][128] | Bs[32][128]; red overlays
    float* As = sm; float* Bs = sm + 4096;
    const int b = blockIdx.z, qt = blockIdx.y;
    const int q0 = qt * 128, k0 = blockIdx.x * 128;
    const float* Tb = TH + (size_t)b * MIDC * TN;
    const float* Pb = PH + (size_t)b * MIDC * TN;
    const int tid = threadIdx.x;
    const int tx = tid & 15, ty = tid >> 4;      // tx: k-oct, ty: q-oct

    u64 acc[4][8];                               // pairs along q  x  8 k
#pragma unroll
    for (int i = 0; i < 4; i++)
#pragma unroll
        for (int j = 0; j < 8; j++) acc[i][j] = 0ULL;

    for (int mt = 0; mt < MIDC; mt += 32) {
#pragma unroll
        for (int t = 0; t < 4; t++) {
            int f4 = tid + t * 256;              // 0..1023
            int mm = f4 >> 5, c4 = (f4 & 31) << 2;
            *(float4*)&As[mm * 128 + c4] = *(const float4*)&Tb[(size_t)(mt + mm) * TN + q0 + c4];
            *(float4*)&Bs[mm * 128 + c4] = *(const float4*)&Pb[(size_t)(mt + mm) * TN + k0 + c4];
        }
        __syncthreads();
#pragma unroll 8
        for (int mm = 0; mm < 32; mm++) {
            ulonglong2 a01 = *(ulonglong2*)&As[mm * 128 + ty * 8];
            ulonglong2 a23 = *(ulonglong2*)&As[mm * 128 + ty * 8 + 4];
            float4 b0 = *(float4*)&Bs[mm * 128 + tx * 8];
            float4 b1 = *(float4*)&Bs[mm * 128 + tx * 8 + 4];
            u64 aa[4] = { a01.x, a01.y, a23.x, a23.y };
            u64 bb[8] = { splat2(b0.x), splat2(b0.y), splat2(b0.z), splat2(b0.w),
                          splat2(b1.x), splat2(b1.y), splat2(b1.z), splat2(b1.w) };
#pragma unroll
            for (int i = 0; i < 4; i++)
#pragma unroll
                for (int j = 0; j < 8; j++)
                    acc[i][j] = fma2_(aa[i], bb[j], acc[i][j]);
        }
        __syncthreads();
    }

    // epilogue: exp (packed), store E^T, per-thread column partials
    float cp[8];
    float* Eb = ET + (size_t)b * TN * TN;
#pragma unroll
    for (int j = 0; j < 8; j++) {
        u64 e0 = fexp2v(acc[0][j]);
        u64 e1 = fexp2v(acc[1][j]);
        u64 e2 = fexp2v(acc[2][j]);
        u64 e3 = fexp2v(acc[3][j]);
        float* row = Eb + (size_t)(k0 + tx * 8 + j) * TN + q0 + ty * 8;
        *(ulonglong2*)(row)     = make_ulonglong2(e0, e1);
        *(ulonglong2*)(row + 4) = make_ulonglong2(e2, e3);
        u64 s2 = add2_(add2_(e0, e1), add2_(e2, e3));
        float lo, hi; upk2(s2, lo, hi);
        cp[j] = lo + hi;
    }
    __syncthreads();                              // done with As/Bs; reuse as red[16][133]
#pragma unroll
    for (int j = 0; j < 8; j++) sm[ty * 133 + tx * 8 + j] = cp[j];
    __syncthreads();
    if (tid < 128) {
        float z = 0.f;
#pragma unroll
        for (int t = 0; t < 16; t++) z += sm[t * 133 + tid];
        Zp[((qt * BATCH + b) << 11) + k0 + tid] = z;
    }
}

// ---------------------------------------------------------------------------
// 3) invZ = 1 / sum of 16 qtile partials; then scale g in place by invZ[k].
// ---------------------------------------------------------------------------
__global__ void __launch_bounds__(256)
invz_kernel(const float* __restrict__ Zp, float* __restrict__ invZ)
{
    int idx = blockIdx.x * 256 + threadIdx.x;    // 16384 = b*2048+k
    float z = 0.f;
#pragma unroll
    for (int t = 0; t < 16; t++) z += Zp[t * 16384 + idx];
    invZ[idx] = 1.0f / z;
}

__global__ void __launch_bounds__(256)
scaleg_kernel(float* __restrict__ G, const float* __restrict__ invZ)
{
    int idx = blockIdx.x * 256 + threadIdx.x;    // 1048576; [b][k][m]
    G[idx] *= invZ[idx >> 6];
}

// ---------------------------------------------------------------------------
// 4) y^T[m][q] = sum_k E^T[k][q] * g[k][m]   (split-K=4, deterministic)
// ---------------------------------------------------------------------------
__global__ void __launch_bounds__(256)
attn_y_kernel(const float* __restrict__ ET, const float* __restrict__ G,
              float* __restrict__ Y4)
{
    __shared__ float As[32 * 256];               // E^T chunk [kk][q]
    __shared__ float Bs[32 * 64];                // g chunk   [kk][m]
    const int sp = blockIdx.x, qt = blockIdx.y, b = blockIdx.z;
    const int q0 = qt * 256;
    const float* Eb = ET + (size_t)b * TN * TN;
    const float* Gb = G + (size_t)b * TN * MIDC;
    const int tid = threadIdx.x;
    const int tx = tid & 7, ty = tid >> 3;       // tx: m-oct, ty: q-oct (32)

    u64 acc[4][8];
#pragma unroll
    for (int i = 0; i < 4; i++)
#pragma unroll
        for (int j = 0; j < 8; j++) acc[i][j] = 0ULL;

    const int kend = sp * 512 + 512;
    for (int kt = sp * 512; kt < kend; kt += 32) {
#pragma unroll
        for (int t = 0; t < 8; t++) {
            int f4 = tid + t * 256;              // 0..2047
            int kk = f4 >> 6, c4 = (f4 & 63) << 2;
            *(float4*)&As[kk * 256 + c4] =
                *(const float4*)&Eb[(size_t)(kt + kk) * TN + q0 + c4];
        }
#pragma unroll
        for (int t = 0; t < 2; t++) {
            int id = tid + t * 256;              // 0..511
            int kk = id >> 4, c4 = (id & 15) << 2;
            *(float4*)&Bs[kk * 64 + c4] = *(const float4*)&Gb[(size_t)(kt + kk) * 64 + c4];
        }
        __syncthreads();
#pragma unroll 8
        for (int kk = 0; kk < 32; kk++) {
            ulonglong2 a01 = *(ulonglong2*)&As[kk * 256 + ty * 8];
            ulonglong2 a23 = *(ulonglong2*)&As[kk * 256 + ty * 8 + 4];
            float4 b0 = *(float4*)&Bs[kk * 64 + tx * 8];
            float4 b1 = *(float4*)&Bs[kk * 64 + tx * 8 + 4];
            u64 aa[4] = { a01.x, a01.y, a23.x, a23.y };
            u64 bb[8] = { splat2(b0.x), splat2(b0.y), splat2(b0.z), splat2(b0.w),
                          splat2(b1.x), splat2(b1.y), splat2(b1.z), splat2(b1.w) };
#pragma unroll
            for (int i = 0; i < 4; i++)
#pragma unroll
                for (int j = 0; j < 8; j++)
                    acc[i][j] = fma2_(aa[i], bb[j], acc[i][j]);
        }
        __syncthreads();
    }

    float* Yo = Y4 + ((size_t)sp * BATCH + b) * MIDC * TN;
#pragma unroll
    for (int j = 0; j < 8; j++) {
        float* row = Yo + (size_t)(tx * 8 + j) * TN + q0 + ty * 8;
        *(ulonglong2*)(row)     = make_ulonglong2(acc[0][j], acc[1][j]);
        *(ulonglong2*)(row + 4) = make_ulonglong2(acc[2][j], acc[3][j]);
    }
}

// ---------------------------------------------------------------------------
// 5) refined[q][o] = relu( sum_m (y4 summed)[m][q] * rw[o][m] + rb[o] )
//    Sums the 4 split-K partials inline while loading A (no reduce pass).
// ---------------------------------------------------------------------------
__global__ void __launch_bounds__(256)
refine_kernel(const float* __restrict__ Y4, const float* __restrict__ RW,
              const float* __restrict__ RB, float* __restrict__ R)
{
    __shared__ float As[32 * 128];               // y^T chunk [mm][q]
    __shared__ float Bs[32 * 128];               // rw^T chunk [mm][o]
    const int b = blockIdx.z;
    const int q0 = blockIdx.x * 128;
    const float* Yb = Y4 + (size_t)b * MIDC * TN;
    const int tid = threadIdx.x;
    const int tx = tid & 15, ty = tid >> 4;      // tx: o-oct, ty: q-oct

    u64 acc[8][4];                               // 8 q  x  pairs along o
#pragma unroll
    for (int i = 0; i < 8; i++)
#pragma unroll
        for (int j = 0; j < 4; j++) acc[i][j] = 0ULL;

    const size_t PS = (size_t)BATCH * MIDC * TN; // split-K partial stride
    for (int mt = 0; mt < MIDC; mt += 32) {
#pragma unroll
        for (int t = 0; t < 4; t++) {
            int f4 = tid + t * 256;              // 0..1023
            int mm = f4 >> 5, c4 = (f4 & 31) << 2;
            size_t off = (size_t)(mt + mm) * TN + q0 + c4;
            float4 y0 = *(const float4*)&Yb[off];
            float4 y1 = *(const float4*)&Yb[off + PS];
            float4 y2 = *(const float4*)&Yb[off + 2 * PS];
            float4 y3 = *(const float4*)&Yb[off + 3 * PS];
            *(float4*)&As[mm * 128 + c4] = make_float4(
                (y0.x + y1.x) + (y2.x + y3.x), (y0.y + y1.y) + (y2.y + y3.y),
                (y0.z + y1.z) + (y2.z + y3.z), (y0.w + y1.w) + (y2.w + y3.w));
        }
#pragma unroll
        for (int t = 0; t < 2; t++) {            // rw^T: 2048 elems per chunk? no: 4096
            int f4 = tid + t * 256;              // need 1024 f4 -> 4 per thread
            int o = f4 >> 3, c4 = (f4 & 7) << 2;
            float4 w4 = *(const float4*)&RW[o * MIDC + mt + c4];
            Bs[(c4 + 0) * 128 + o] = w4.x;
            Bs[(c4 + 1) * 128 + o] = w4.y;
            Bs[(c4 + 2) * 128 + o] = w4.z;
            Bs[(c4 + 3) * 128 + o] = w4.w;
        }
        // second half of rw^T (o 64..127): f4 512..1023
#pragma unroll
        for (int t = 2; t < 4; t++) {
            int f4 = tid + t * 256;
            int o = f4 >> 3, c4 = (f4 & 7) << 2;
            float4 w4 = *(const float4*)&RW[o * MIDC + mt + c4];
            Bs[(c4 + 0) * 128 + o] = w4.x;
            Bs[(c4 + 1) * 128 + o] = w4.y;
            Bs[(c4 + 2) * 128 + o] = w4.z;
            Bs[(c4 + 3) * 128 + o] = w4.w;
        }
        __syncthreads();
#pragma unroll 8
        for (int mm = 0; mm < 32; mm++) {
            float4 a0 = *(float4*)&As[mm * 128 + ty * 8];
            float4 a1 = *(float4*)&As[mm * 128 + ty * 8 + 4];
            ulonglong2 b01 = *(ulonglong2*)&Bs[mm * 128 + tx * 8];
            ulonglong2 b23 = *(ulonglong2*)&Bs[mm * 128 + tx * 8 + 4];
            u64 aa[8] = { splat2(a0.x), splat2(a0.y), splat2(a0.z), splat2(a0.w),
                          splat2(a1.x), splat2(a1.y), splat2(a1.z), splat2(a1.w) };
            u64 bb[4] = { b01.x, b01.y, b23.x, b23.y };
#pragma unroll
            for (int i = 0; i < 8; i++)
#pragma unroll
                for (int j = 0; j < 4; j++)
                    acc[i][j] = fma2_(aa[i], bb[j], acc[i][j]);
        }
        __syncthreads();
    }

    float* Rb = R + (size_t)b * TN * OUTC;
    float rbv[8];
#pragma unroll
    for (int j = 0; j < 8; j++) rbv[j] = RB[tx * 8 + j];
#pragma unroll
    for (int i = 0; i < 8; i++) {
        float v[8];
#pragma unroll
        for (int j2 = 0; j2 < 4; j2++) upk2(acc[i][j2], v[2 * j2], v[2 * j2 + 1]);
#pragma unroll
        for (int j = 0; j < 8; j++) v[j] = fmaxf(v[j] + rbv[j], 0.f);
        size_t row = (size_t)(q0 + ty * 8 + i) * OUTC + tx * 8;
        *(float4*)&Rb[row]     = make_float4(v[0], v[1], v[2], v[3]);
        *(float4*)&Rb[row + 4] = make_float4(v[4], v[5], v[6], v[7]);
    }
}

// ---------------------------------------------------------------------------
// 6) out[b,c,t,n] = refined[b][q][o] + pc  with q=(n&15)*128+c, o=t*32+(n>>4)
// ---------------------------------------------------------------------------
__global__ void __launch_bounds__(256)
scatter_kernel(const float* __restrict__ R, const float* __restrict__ pc,
               float* __restrict__ out)
{
    int idx = blockIdx.x * 256 + threadIdx.x;    // 2097152
    int b = idx >> 18;
    int r = idx & 262143;
    int c = r >> 11;
    int t = (r >> 9) & 3;
    int n = r & 511;
    int q = ((n & 15) << 7) + c;
    int o = (t << 5) + (n >> 4);
    out[idx] = R[(((b << 11) + q) << 7) + o] + pc[idx];
}

// ---------------------------------------------------------------------------
// Host launcher
// ---------------------------------------------------------------------------
extern "C" void kernel_launch(void* const* d_in, const int* in_sizes, int n_in,
                              void* d_out, int out_size)
{
    const float* pc = (const float*)d_in[0];
    const float* tw = (const float*)d_in[1];
    const float* tb = (const float*)d_in[2];
    const float* pw = (const float*)d_in[3];
    const float* pb = (const float*)d_in[4];
    const float* gw = (const float*)d_in[5];
    const float* gb = (const float*)d_in[6];
    const float* rw = (const float*)d_in[7];
    const float* rb = (const float*)d_in[8];
    float* out = (float*)d_out;

    float *theta, *phi, *gg, *ET, *Zp, *invZ, *y4, *ref;
    cudaGetSymbolAddress((void**)&theta, g_theta);
    cudaGetSymbolAddress((void**)&phi,   g_phi);
    cudaGetSymbolAddress((void**)&gg,    g_g);
    cudaGetSymbolAddress((void**)&ET,    g_ET);
    cudaGetSymbolAddress((void**)&Zp,    g_Zp);
    cudaGetSymbolAddress((void**)&invZ,  g_invZ);
    cudaGetSymbolAddress((void**)&y4,    g_y4);
    cudaGetSymbolAddress((void**)&ref,   g_ref);

    proj_kernel  <<<dim3(16, 3, BATCH), 256>>>(pc, tw, tb, pw, pb, gw, gb,
                                               theta, phi, gg);
    scores_kernel<<<dim3(16, 16, BATCH), 256>>>(theta, phi, ET, Zp);
    invz_kernel  <<<64, 256>>>(Zp, invZ);
    scaleg_kernel<<<4096, 256>>>(gg, invZ);
    attn_y_kernel<<<dim3(4, 8, BATCH), 256>>>(ET, gg, y4);
    refine_kernel<<<dim3(16, 1, BATCH), 256>>>(y4, rw, rb, ref);
    scatter_kernel<<<8192, 256>>>(ref, pc, out);
}

// round 7
// speedup vs baseline: 2.3047x; 1.3312x over previous
#include <cuda_runtime.h>
#include <cuda_bf16.h>

#define BATCH 8
#define CH    128
#define MIDC  64
#define OUTC  128
#define TN    2048

typedef unsigned long long u64;
typedef unsigned int u32;
typedef unsigned short u16;

// ---------------------------------------------------------------------------
// Scratch (device globals; allocation-free per harness rules)
// ---------------------------------------------------------------------------
__device__ __nv_bfloat16 g_thhi[BATCH * TN * MIDC];     // theta hi [b][q][m]
__device__ __nv_bfloat16 g_thlo[BATCH * TN * MIDC];
__device__ __nv_bfloat16 g_phhi[BATCH * TN * MIDC];     // phi hi [b][k][m]
__device__ __nv_bfloat16 g_phlo[BATCH * TN * MIDC];
__device__ float         g_g   [BATCH * TN * MIDC];     // g fp32 [b][k][m]
__device__ __nv_bfloat16 g_Ehi [(size_t)BATCH * TN * TN]; // exp(s) hi [b][q][k]
__device__ __nv_bfloat16 g_Elo [(size_t)BATCH * TN * TN];
__device__ float g_Zp  [16 * BATCH * TN];
__device__ float g_invZ[BATCH * TN];
__device__ __nv_bfloat16 g_gsThi[BATCH * MIDC * TN];    // (g*invZ)^T hi [b][m][k]
__device__ __nv_bfloat16 g_gsTlo[BATCH * MIDC * TN];
__device__ float g_yT [BATCH * MIDC * TN];              // y^T [b][m][q]
__device__ float g_ref[BATCH * TN * OUTC];              // [b][q][o]

// ---------------------------------------------------------------------------
// PTX helpers (base ISA only -- no 'a'-gated features)
// ---------------------------------------------------------------------------
__device__ __forceinline__ u32 smem_u32(const void* p) {
    u32 a; asm("{ .reg .u64 t; cvta.to.shared.u64 t, %1; cvt.u32.u64 %0, t; }"
               : "=r"(a) : "l"(p)); return a;
}
#define SWZ128(x) ((x) ^ (((x) >> 3) & 0x70))

__device__ __forceinline__ void ldsm4(u32* r, u32 addr) {
    asm volatile("ldmatrix.sync.aligned.m8n8.x4.shared.b16 {%0,%1,%2,%3}, [%4];"
        : "=r"(r[0]), "=r"(r[1]), "=r"(r[2]), "=r"(r[3]) : "r"(addr));
}
__device__ __forceinline__ void mma16816(float* d, const u32* a, u32 b0, u32 b1) {
    asm volatile("mma.sync.aligned.m16n8k16.row.col.f32.bf16.bf16.f32 "
        "{%0,%1,%2,%3}, {%4,%5,%6,%7}, {%8,%9}, {%0,%1,%2,%3};"
        : "+f"(d[0]), "+f"(d[1]), "+f"(d[2]), "+f"(d[3])
        : "r"(a[0]), "r"(a[1]), "r"(a[2]), "r"(a[3]), "r"(b0), "r"(b1));
}

// ---------------------------------------------------------------------------
// fp32x2 + fast exp helpers (FFMA2 scalar path for proj/refine)
// ---------------------------------------------------------------------------
__device__ __forceinline__ u64 splat2(float x) {
    u64 r; asm("mov.b64 %0,{%1,%1};" : "=l"(r) : "f"(x)); return r;
}
__device__ __forceinline__ u64 fma2_(u64 a, u64 b, u64 c) {
    u64 d; asm("fma.rn.f32x2 %0,%1,%2,%3;" : "=l"(d) : "l"(a), "l"(b), "l"(c)); return d;
}
__device__ __forceinline__ void upk2(u64 p, float& a, float& b) {
    asm("mov.b64 {%0,%1},%2;" : "=f"(a), "=f"(b) : "l"(p));
}
__device__ __forceinline__ float fexp(float x) {
    const float L2E = 1.4426950408889634f;
    float z = fmaf(x, L2E, 12582912.0f);
    float n = z - 12582912.0f;
    float f = fmaf(x, L2E, -n);
    float p =          1.3333558146e-3f;
    p = fmaf(p, f,     9.6181291076e-3f);
    p = fmaf(p, f,     5.5504108665e-2f);
    p = fmaf(p, f,     2.4022650696e-1f);
    p = fmaf(p, f,     6.9314718056e-1f);
    p = fmaf(p, f,     1.0f);
    int ni = __float_as_int(z) - 0x4B400000;
    return p * __int_as_float((ni + 127) << 23);
}
__device__ __forceinline__ u32 pkbf(__nv_bfloat16 a, __nv_bfloat16 b) {
    return (u32)__bfloat16_as_ushort(a) | ((u32)__bfloat16_as_ushort(b) << 16);
}
__device__ __forceinline__ u32 pk_hi2(float x, float y) {
    return pkbf(__float2bfloat16(x), __float2bfloat16(y));
}
__device__ __forceinline__ u32 pk_lo2(float x, float y) {
    __nv_bfloat16 hx = __float2bfloat16(x), hy = __float2bfloat16(y);
    return pkbf(__float2bfloat16(x - __bfloat162float(hx)),
                __float2bfloat16(y - __bfloat162float(hy)));
}

// ---------------------------------------------------------------------------
// 1) Projections: relu(W[64x128]*pc[128x2048]+b).
//    theta,phi -> bf16 hi/lo [tn][64];  g -> fp32 [tn][64].
// ---------------------------------------------------------------------------
__global__ void __launch_bounds__(256)
proj_kernel(const float* __restrict__ pc,
            const float* __restrict__ tw, const float* __restrict__ tb,
            const float* __restrict__ pw, const float* __restrict__ pb,
            const float* __restrict__ gw, const float* __restrict__ gb)
{
    __shared__ float As[32 * 64];
    __shared__ float Bs[32 * 128];
    const int b = blockIdx.z, pj = blockIdx.y;
    const int n0 = blockIdx.x * 128;
    const float *W, *bi;
    if (pj == 0)      { W = tw; bi = tb; }
    else if (pj == 1) { W = pw; bi = pb; }
    else              { W = gw; bi = gb; }
    const float* pcb = pc + (size_t)b * CH * TN;
    const int tid = threadIdx.x;
    const int tx = tid & 15, ty = tid >> 4;

    u64 acc[4][4];
#pragma unroll
    for (int i = 0; i < 4; i++)
#pragma unroll
        for (int j = 0; j < 4; j++) acc[i][j] = 0ULL;

    for (int ct = 0; ct < 128; ct += 32) {
#pragma unroll
        for (int t = 0; t < 2; t++) {
            int f4 = tid + t * 256;
            int m = f4 >> 3, c4 = (f4 & 7) << 2;
            float4 w4 = *(const float4*)&W[m * 128 + ct + c4];
            As[(c4 + 0) * 64 + m] = w4.x;  As[(c4 + 1) * 64 + m] = w4.y;
            As[(c4 + 2) * 64 + m] = w4.z;  As[(c4 + 3) * 64 + m] = w4.w;
        }
#pragma unroll
        for (int t = 0; t < 4; t++) {
            int f4 = tid + t * 256;
            int cc = f4 >> 5, c4 = (f4 & 31) << 2;
            *(float4*)&Bs[cc * 128 + c4] =
                *(const float4*)&pcb[(size_t)(ct + cc) * TN + n0 + c4];
        }
        __syncthreads();
#pragma unroll 8
        for (int cc = 0; cc < 32; cc++) {
            float4 av = *(float4*)&As[cc * 64 + ty * 4];
            ulonglong2 b01 = *(ulonglong2*)&Bs[cc * 128 + tx * 8];
            ulonglong2 b23 = *(ulonglong2*)&Bs[cc * 128 + tx * 8 + 4];
            u64 aa[4] = { splat2(av.x), splat2(av.y), splat2(av.z), splat2(av.w) };
            u64 bb[4] = { b01.x, b01.y, b23.x, b23.y };
#pragma unroll
            for (int i = 0; i < 4; i++)
#pragma unroll
                for (int j = 0; j < 4; j++)
                    acc[i][j] = fma2_(aa[i], bb[j], acc[i][j]);
        }
        __syncthreads();
    }

    float v[4][8];
#pragma unroll
    for (int i = 0; i < 4; i++) {
#pragma unroll
        for (int j2 = 0; j2 < 4; j2++) upk2(acc[i][j2], v[i][2 * j2], v[i][2 * j2 + 1]);
        float bv = bi[ty * 4 + i];
#pragma unroll
        for (int j = 0; j < 8; j++) v[i][j] = fmaxf(v[i][j] + bv, 0.f);
    }
    if (pj < 2) {
        __nv_bfloat16* oh = (pj == 0 ? g_thhi : g_phhi) + (size_t)b * TN * MIDC;
        __nv_bfloat16* ol = (pj == 0 ? g_thlo : g_phlo) + (size_t)b * TN * MIDC;
#pragma unroll
        for (int j = 0; j < 8; j++) {
            int tn = n0 + tx * 8 + j;
            *(uint2*)&oh[(size_t)tn * MIDC + ty * 4] =
                make_uint2(pk_hi2(v[0][j], v[1][j]), pk_hi2(v[2][j], v[3][j]));
            *(uint2*)&ol[(size_t)tn * MIDC + ty * 4] =
                make_uint2(pk_lo2(v[0][j], v[1][j]), pk_lo2(v[2][j], v[3][j]));
        }
    } else {
        float* ob = g_g + (size_t)b * TN * MIDC;
#pragma unroll
        for (int j = 0; j < 8; j++)
            *(float4*)&ob[(size_t)(n0 + tx * 8 + j) * MIDC + ty * 4] =
                make_float4(v[0][j], v[1][j], v[2][j], v[3][j]);
    }
}

// ---------------------------------------------------------------------------
// 2) scores via warp-MMA bf16 3-pass: s = theta*phi^T, then exp + hi/lo split,
//    fused column-sum partials, coalesced E store.
// smem: operands AH 0 / AL 16K / BH 32K / BL 48K ; epilogue staging overlays
//       EHI [0,33792) ELO [33792,67584), both 128 rows x 132 bf16.
// ---------------------------------------------------------------------------
#define SC_SMEM 67584

__global__ void __launch_bounds__(256)
scores_kernel()
{
    extern __shared__ char smem[];
    const u32 sb = smem_u32(smem);
    const int b = blockIdx.z, qt = blockIdx.y, kt = blockIdx.x;
    const int q0 = qt * 128, k0 = kt * 128;
    const int tid = threadIdx.x, wid = tid >> 5, lane = tid & 31;
    const int wq = wid >> 1, wk = wid & 1;

    // load 4 operand tiles (128 rows x 64 bf16) swizzled
    {
        const __nv_bfloat16* s0 = g_thhi + (size_t)(b * TN + q0) * MIDC;
        const __nv_bfloat16* s1 = g_thlo + (size_t)(b * TN + q0) * MIDC;
        const __nv_bfloat16* s2 = g_phhi + (size_t)(b * TN + k0) * MIDC;
        const __nv_bfloat16* s3 = g_phlo + (size_t)(b * TN + k0) * MIDC;
        const __nv_bfloat16* srcs[4] = { s0, s1, s2, s3 };
#pragma unroll
        for (int it = 0; it < 16; it++) {
            int idx = tid + it * 256;            // 0..4095 16B units
            int mat = idx >> 10, row = (idx >> 3) & 127, u = idx & 7;
            uint4 v = *(const uint4*)(srcs[mat] + (size_t)row * MIDC + u * 8);
            *(uint4*)(smem + mat * 16384 + SWZ128(row * 128 + u * 16)) = v;
        }
    }
    __syncthreads();

    float acc[2][8][4];
#pragma unroll
    for (int i = 0; i < 2; i++)
#pragma unroll
        for (int j = 0; j < 8; j++)
#pragma unroll
            for (int r = 0; r < 4; r++) acc[i][j][r] = 0.f;

    const u32 baseA[2] = { sb, sb + 16384 };
    const u32 baseB[2] = { sb + 32768, sb + 49152 };
    const int pa[3] = { 0, 0, 1 }, pbx[3] = { 0, 1, 0 };
    const int arow = wq * 32 + (lane & 15);
    const int acolx = (lane >> 4) << 4;
    const int brow = wk * 64 + (lane & 7) + ((lane >> 4) << 3);
    const int bcolx = ((lane >> 3) & 1) << 4;

#pragma unroll
    for (int p = 0; p < 3; p++) {
        u32 bA = baseA[pa[p]], bB = baseB[pbx[p]];
#pragma unroll
        for (int ks = 0; ks < 4; ks++) {
            int kb = ks * 32;
            u32 a0[4], a1[4];
            ldsm4(a0, bA + SWZ128((arow) * 128 + kb + acolx));
            ldsm4(a1, bA + SWZ128((arow + 16) * 128 + kb + acolx));
#pragma unroll
            for (int jp = 0; jp < 4; jp++) {
                u32 bb[4];
                ldsm4(bb, bB + SWZ128((brow + jp * 16) * 128 + kb + bcolx));
                mma16816(acc[0][2 * jp],     a0, bb[0], bb[1]);
                mma16816(acc[0][2 * jp + 1], a0, bb[2], bb[3]);
                mma16816(acc[1][2 * jp],     a1, bb[0], bb[1]);
                mma16816(acc[1][2 * jp + 1], a1, bb[2], bb[3]);
            }
        }
    }
    __syncthreads();                             // operands dead; stage E

    // exp + hi/lo split into staging (rows stride 132 bf16 = 264 B)
#pragma unroll
    for (int i = 0; i < 2; i++) {
        int qr = wq * 32 + i * 16 + (lane >> 2);
#pragma unroll
        for (int j = 0; j < 8; j++) {
            int kc = wk * 64 + j * 8 + 2 * (lane & 3);
            float e00 = fexp(acc[i][j][0]), e01 = fexp(acc[i][j][1]);
            float e10 = fexp(acc[i][j][2]), e11 = fexp(acc[i][j][3]);
            *(u32*)(smem +         qr * 264 + kc * 2)       = pk_hi2(e00, e01);
            *(u32*)(smem +        (qr + 8) * 264 + kc * 2)  = pk_hi2(e10, e11);
            *(u32*)(smem + 33792 + qr * 264 + kc * 2)       = pk_lo2(e00, e01);
            *(u32*)(smem + 33792 + (qr + 8) * 264 + kc * 2) = pk_lo2(e10, e11);
        }
    }
    __syncthreads();

    // column-sum partials over this qtile's 128 q rows
    if (tid < 128) {
        const __nv_bfloat16* ehs = (const __nv_bfloat16*)smem;
        const __nv_bfloat16* els = (const __nv_bfloat16*)(smem + 33792);
        float z = 0.f;
#pragma unroll 4
        for (int q = 0; q < 128; q++)
            z += __bfloat162float(ehs[q * 132 + tid]) + __bfloat162float(els[q * 132 + tid]);
        g_Zp[(qt * BATCH + b) * TN + k0 + tid] = z;
    }

    // coalesced copy-out: 256 row-tasks (128 rows x {hi,lo})
    for (int task = wid; task < 256; task += 8) {
        int mat = task >> 7, row = task & 127;
        uint2 v = *(const uint2*)(smem + mat * 33792 + row * 264 + lane * 8);
        __nv_bfloat16* dst = (mat ? g_Elo : g_Ehi)
            + (size_t)(b * TN + q0 + row) * TN + k0 + lane * 4;
        *(uint2*)dst = v;
    }
}

// ---------------------------------------------------------------------------
// 3) invZ, then scale+transpose+split g -> gsT hi/lo [m][k] bf16
// ---------------------------------------------------------------------------
__global__ void __launch_bounds__(256)
invz_kernel()
{
    int idx = blockIdx.x * 256 + threadIdx.x;    // 16384 = b*2048+k
    float z = 0.f;
#pragma unroll
    for (int t = 0; t < 16; t++) z += g_Zp[t * 16384 + idx];
    g_invZ[idx] = 1.0f / z;
}

__global__ void __launch_bounds__(256)
scalegT_kernel()
{
    __shared__ float s[64][65];
    const int k0 = blockIdx.x * 64, b = blockIdx.y;
    const int tid = threadIdx.x;
#pragma unroll
    for (int t = 0; t < 4; t++) {
        int f4 = tid + t * 256;
        int row = f4 >> 4, c4 = (f4 & 15) << 2;
        float iz = g_invZ[b * TN + k0 + row];
        float4 v = *(const float4*)&g_g[(size_t)(b * TN + k0 + row) * MIDC + c4];
        s[row][c4 + 0] = v.x * iz;  s[row][c4 + 1] = v.y * iz;
        s[row][c4 + 2] = v.z * iz;  s[row][c4 + 3] = v.w * iz;
    }
    __syncthreads();
    int m = tid >> 2, kk0 = (tid & 3) << 4;      // 16 k per thread
    u32 hw[8], lw[8];
#pragma unroll
    for (int j = 0; j < 8; j++) {
        float v0 = s[kk0 + 2 * j][m], v1 = s[kk0 + 2 * j + 1][m];
        hw[j] = pk_hi2(v0, v1);
        lw[j] = pk_lo2(v0, v1);
    }
    size_t doff = (size_t)(b * MIDC + m) * TN + k0 + kk0;
    *(uint4*)&g_gsThi[doff]     = make_uint4(hw[0], hw[1], hw[2], hw[3]);
    *(uint4*)&g_gsThi[doff + 8] = make_uint4(hw[4], hw[5], hw[6], hw[7]);
    *(uint4*)&g_gsTlo[doff]     = make_uint4(lw[0], lw[1], lw[2], lw[3]);
    *(uint4*)&g_gsTlo[doff + 8] = make_uint4(lw[4], lw[5], lw[6], lw[7]);
}

// ---------------------------------------------------------------------------
// 4) attn_y via warp-MMA bf16 3-pass: y[q][m] = sum_k E[q][k]*gs[k][m]
// smem: AH 0 / AL 16K (128x64 bf16 swz); BH 32768 / BL 40960 (64x64).
// Epilogue stages D fp32 [128][65] (reusing smem) and writes y^T.
// ---------------------------------------------------------------------------
#define AT_SMEM 49152

__global__ void __launch_bounds__(256)
attn_y_kernel()
{
    extern __shared__ char smem[];
    const u32 sb = smem_u32(smem);
    const int qt = blockIdx.x, b = blockIdx.y;
    const int q0 = qt * 128;
    const int tid = threadIdx.x, wid = tid >> 5, lane = tid & 31;
    const int qg = wid >> 1, mg = wid & 1;

    float acc[2][4][4];
#pragma unroll
    for (int i = 0; i < 2; i++)
#pragma unroll
        for (int j = 0; j < 4; j++)
#pragma unroll
            for (int r = 0; r < 4; r++) acc[i][j][r] = 0.f;

    const u32 baseA[2] = { sb, sb + 16384 };
    const u32 baseB[2] = { sb + 32768, sb + 40960 };
    const int pa[3] = { 0, 0, 1 }, pbx[3] = { 0, 1, 0 };
    const int arow = qg * 32 + (lane & 15);
    const int acolx = (lane >> 4) << 4;
    const int brow = mg * 32 + (lane & 7) + ((lane >> 4) << 3);
    const int bcolx = ((lane >> 3) & 1) << 4;

    for (int ch = 0; ch < 32; ch++) {
        const int kc = ch * 64;
#pragma unroll
        for (int it = 0; it < 8; it++) {         // E hi/lo [128 q][64 k]
            int idx = tid + it * 256;
            int mat = idx >> 10, row = (idx >> 3) & 127, u = idx & 7;
            const __nv_bfloat16* src = (mat ? g_Elo : g_Ehi)
                + (size_t)(b * TN + q0 + row) * TN + kc + u * 8;
            *(uint4*)(smem + mat * 16384 + SWZ128(row * 128 + u * 16)) =
                *(const uint4*)src;
        }
#pragma unroll
        for (int it = 0; it < 4; it++) {         // gsT hi/lo [64 m][64 k]
            int idx = tid + it * 256;
            int mat = idx >> 9, row = (idx >> 3) & 63, u = idx & 7;
            const __nv_bfloat16* src = (mat ? g_gsTlo : g_gsThi)
                + (size_t)(b * MIDC + row) * TN + kc + u * 8;
            *(uint4*)(smem + 32768 + mat * 8192 + SWZ128(row * 128 + u * 16)) =
                *(const uint4*)src;
        }
        __syncthreads();
#pragma unroll
        for (int p = 0; p < 3; p++) {
            u32 bA = baseA[pa[p]], bB = baseB[pbx[p]];
#pragma unroll
            for (int ks = 0; ks < 4; ks++) {
                int kb = ks * 32;
                u32 a0[4], a1[4];
                ldsm4(a0, bA + SWZ128((arow) * 128 + kb + acolx));
                ldsm4(a1, bA + SWZ128((arow + 16) * 128 + kb + acolx));
#pragma unroll
                for (int jp = 0; jp < 2; jp++) {
                    u32 bb[4];
                    ldsm4(bb, bB + SWZ128((brow + jp * 16) * 128 + kb + bcolx));
                    mma16816(acc[0][2 * jp],     a0, bb[0], bb[1]);
                    mma16816(acc[0][2 * jp + 1], a0, bb[2], bb[3]);
                    mma16816(acc[1][2 * jp],     a1, bb[0], bb[1]);
                    mma16816(acc[1][2 * jp + 1], a1, bb[2], bb[3]);
                }
            }
        }
        __syncthreads();
    }

    // epilogue: stage D[128 q][64 m] fp32 (stride 65), write y^T[m][q]
    float* ys = (float*)smem;
#pragma unroll
    for (int i = 0; i < 2; i++) {
        int qr = qg * 32 + i * 16 + (lane >> 2);
#pragma unroll
        for (int j = 0; j < 4; j++) {
            int mc = mg * 32 + j * 8 + 2 * (lane & 3);
            ys[qr * 65 + mc]           = acc[i][j][0];
            ys[qr * 65 + mc + 1]       = acc[i][j][1];
            ys[(qr + 8) * 65 + mc]     = acc[i][j][2];
            ys[(qr + 8) * 65 + mc + 1] = acc[i][j][3];
        }
    }
    __syncthreads();
    for (int m = wid; m < 64; m += 8) {
        float4 f = make_float4(ys[(lane * 4 + 0) * 65 + m], ys[(lane * 4 + 1) * 65 + m],
                               ys[(lane * 4 + 2) * 65 + m], ys[(lane * 4 + 3) * 65 + m]);
        *(float4*)&g_yT[(size_t)(b * MIDC + m) * TN + q0 + lane * 4] = f;
    }
}

// ---------------------------------------------------------------------------
// 5) refine (FFMA2): refined[q][o] = relu(sum_m yT[m][q]*rw[o][m] + rb[o])
// ---------------------------------------------------------------------------
__global__ void __launch_bounds__(256)
refine_kernel(const float* __restrict__ RW, const float* __restrict__ RB)
{
    __shared__ float As[32 * 128];
    __shared__ float Bs[32 * 128];
    const int b = blockIdx.z;
    const int q0 = blockIdx.x * 128;
    const float* Yb = g_yT + (size_t)b * MIDC * TN;
    const int tid = threadIdx.x;
    const int tx = tid & 15, ty = tid >> 4;

    u64 acc[8][4];
#pragma unroll
    for (int i = 0; i < 8; i++)
#pragma unroll
        for (int j = 0; j < 4; j++) acc[i][j] = 0ULL;

    for (int mt = 0; mt < MIDC; mt += 32) {
#pragma unroll
        for (int t = 0; t < 4; t++) {
            int f4 = tid + t * 256;
            int mm = f4 >> 5, c4 = (f4 & 31) << 2;
            *(float4*)&As[mm * 128 + c4] =
                *(const float4*)&Yb[(size_t)(mt + mm) * TN + q0 + c4];
        }
#pragma unroll
        for (int t = 0; t < 4; t++) {
            int f4 = tid + t * 256;
            int o = f4 >> 3, c4 = (f4 & 7) << 2;
            float4 w4 = *(const float4*)&RW[o * MIDC + mt + c4];
            Bs[(c4 + 0) * 128 + o] = w4.x;  Bs[(c4 + 1) * 128 + o] = w4.y;
            Bs[(c4 + 2) * 128 + o] = w4.z;  Bs[(c4 + 3) * 128 + o] = w4.w;
        }
        __syncthreads();
#pragma unroll 8
        for (int mm = 0; mm < 32; mm++) {
            float4 a0 = *(float4*)&As[mm * 128 + ty * 8];
            float4 a1 = *(float4*)&As[mm * 128 + ty * 8 + 4];
            ulonglong2 b01 = *(ulonglong2*)&Bs[mm * 128 + tx * 8];
            ulonglong2 b23 = *(ulonglong2*)&Bs[mm * 128 + tx * 8 + 4];
            u64 aa[8] = { splat2(a0.x), splat2(a0.y), splat2(a0.z), splat2(a0.w),
                          splat2(a1.x), splat2(a1.y), splat2(a1.z), splat2(a1.w) };
            u64 bb[4] = { b01.x, b01.y, b23.x, b23.y };
#pragma unroll
            for (int i = 0; i < 8; i++)
#pragma unroll
                for (int j = 0; j < 4; j++)
                    acc[i][j] = fma2_(aa[i], bb[j], acc[i][j]);
        }
        __syncthreads();
    }

    float* Rb = g_ref + (size_t)b * TN * OUTC;
    float rbv[8];
#pragma unroll
    for (int j = 0; j < 8; j++) rbv[j] = RB[tx * 8 + j];
#pragma unroll
    for (int i = 0; i < 8; i++) {
        float v[8];
#pragma unroll
        for (int j2 = 0; j2 < 4; j2++) upk2(acc[i][j2], v[2 * j2], v[2 * j2 + 1]);
#pragma unroll
        for (int j = 0; j < 8; j++) v[j] = fmaxf(v[j] + rbv[j], 0.f);
        size_t row = (size_t)(q0 + ty * 8 + i) * OUTC + tx * 8;
        *(float4*)&Rb[row]     = make_float4(v[0], v[1], v[2], v[3]);
        *(float4*)&Rb[row + 4] = make_float4(v[4], v[5], v[6], v[7]);
    }
}

// ---------------------------------------------------------------------------
// 6) out[b,c,t,n] = refined[b][q][o] + pc, q=(n&15)*128+c, o=t*32+(n>>4)
// ---------------------------------------------------------------------------
__global__ void __launch_bounds__(256)
scatter_kernel(const float* __restrict__ pc, float* __restrict__ out)
{
    int idx = blockIdx.x * 256 + threadIdx.x;    // 2097152
    int b = idx >> 18;
    int r = idx & 262143;
    int c = r >> 11;
    int t = (r >> 9) & 3;
    int n = r & 511;
    int q = ((n & 15) << 7) + c;
    int o = (t << 5) + (n >> 4);
    out[idx] = g_ref[(((b << 11) + q) << 7) + o] + pc[idx];
}

// ---------------------------------------------------------------------------
// Host launcher
// ---------------------------------------------------------------------------
extern "C" void kernel_launch(void* const* d_in, const int* in_sizes, int n_in,
                              void* d_out, int out_size)
{
    const float* pc = (const float*)d_in[0];
    const float* tw = (const float*)d_in[1];
    const float* tb = (const float*)d_in[2];
    const float* pw = (const float*)d_in[3];
    const float* pb = (const float*)d_in[4];
    const float* gw = (const float*)d_in[5];
    const float* gb = (const float*)d_in[6];
    const float* rw = (const float*)d_in[7];
    const float* rb = (const float*)d_in[8];
    float* out = (float*)d_out;

    cudaFuncSetAttribute(scores_kernel,
                         cudaFuncAttributeMaxDynamicSharedMemorySize, SC_SMEM);
    cudaFuncSetAttribute(attn_y_kernel,
                         cudaFuncAttributeMaxDynamicSharedMemorySize, AT_SMEM);

    proj_kernel   <<<dim3(16, 3, BATCH), 256>>>(pc, tw, tb, pw, pb, gw, gb);
    scores_kernel <<<dim3(16, 16, BATCH), 256, SC_SMEM>>>();
    invz_kernel   <<<64, 256>>>();
    scalegT_kernel<<<dim3(32, BATCH), 256>>>();
    attn_y_kernel <<<dim3(16, BATCH), 256, AT_SMEM>>>();
    refine_kernel <<<dim3(16, 1, BATCH), 256>>>(rw, rb);
    scatter_kernel<<<8192, 256>>>(pc, out);
}

// round 8
// speedup vs baseline: 3.0601x; 1.3278x over previous
#include <cuda_runtime.h>
#include <cuda_bf16.h>

#define BATCH 8
#define CH    128
#define MIDC  64
#define OUTC  128
#define TN    2048

typedef unsigned long long u64;
typedef unsigned int u32;

// ---------------------------------------------------------------------------
// Scratch (device globals; allocation-free per harness rules)
// ---------------------------------------------------------------------------
__device__ __nv_bfloat16 g_thhi[BATCH * TN * MIDC];     // theta hi [b][q][m]
__device__ __nv_bfloat16 g_thlo[BATCH * TN * MIDC];
__device__ __nv_bfloat16 g_phhi[BATCH * TN * MIDC];     // phi hi [b][k][m]
__device__ __nv_bfloat16 g_phlo[BATCH * TN * MIDC];
__device__ float         g_g   [BATCH * TN * MIDC];     // g fp32 [b][k][m]
__device__ __nv_bfloat16 g_Ehi [(size_t)BATCH * TN * TN]; // exp(s) bf16 [b][q][k]
__device__ float g_Zp  [16 * BATCH * TN];
__device__ __nv_bfloat16 g_gsThi[BATCH * MIDC * TN];    // (g*invZ)^T hi [b][m][k]
__device__ __nv_bfloat16 g_gsTlo[BATCH * MIDC * TN];
__device__ float g_yT [BATCH * MIDC * TN];              // y^T [b][m][q]
__device__ float g_ref[BATCH * TN * OUTC];              // [b][q][o]

// ---------------------------------------------------------------------------
// PTX helpers (base ISA only)
// ---------------------------------------------------------------------------
__device__ __forceinline__ u32 smem_u32(const void* p) {
    u32 a; asm("{ .reg .u64 t; cvta.to.shared.u64 t, %1; cvt.u32.u64 %0, t; }"
               : "=r"(a) : "l"(p)); return a;
}
#define SWZ128(x) ((x) ^ (((x) >> 3) & 0x70))

__device__ __forceinline__ void ldsm4(u32* r, u32 addr) {
    asm volatile("ldmatrix.sync.aligned.m8n8.x4.shared.b16 {%0,%1,%2,%3}, [%4];"
        : "=r"(r[0]), "=r"(r[1]), "=r"(r[2]), "=r"(r[3]) : "r"(addr));
}
__device__ __forceinline__ void mma16816(float* d, const u32* a, u32 b0, u32 b1) {
    asm volatile("mma.sync.aligned.m16n8k16.row.col.f32.bf16.bf16.f32 "
        "{%0,%1,%2,%3}, {%4,%5,%6,%7}, {%8,%9}, {%0,%1,%2,%3};"
        : "+f"(d[0]), "+f"(d[1]), "+f"(d[2]), "+f"(d[3])
        : "r"(a[0]), "r"(a[1]), "r"(a[2]), "r"(a[3]), "r"(b0), "r"(b1));
}

// fp32x2 + fast exp helpers
__device__ __forceinline__ u64 splat2(float x) {
    u64 r; asm("mov.b64 %0,{%1,%1};" : "=l"(r) : "f"(x)); return r;
}
__device__ __forceinline__ u64 fma2_(u64 a, u64 b, u64 c) {
    u64 d; asm("fma.rn.f32x2 %0,%1,%2,%3;" : "=l"(d) : "l"(a), "l"(b), "l"(c)); return d;
}
__device__ __forceinline__ void upk2(u64 p, float& a, float& b) {
    asm("mov.b64 {%0,%1},%2;" : "=f"(a), "=f"(b) : "l"(p));
}
__device__ __forceinline__ float fexp(float x) {
    const float L2E = 1.4426950408889634f;
    float z = fmaf(x, L2E, 12582912.0f);
    float n = z - 12582912.0f;
    float f = fmaf(x, L2E, -n);
    float p =          1.3333558146e-3f;
    p = fmaf(p, f,     9.6181291076e-3f);
    p = fmaf(p, f,     5.5504108665e-2f);
    p = fmaf(p, f,     2.4022650696e-1f);
    p = fmaf(p, f,     6.9314718056e-1f);
    p = fmaf(p, f,     1.0f);
    int ni = __float_as_int(z) - 0x4B400000;
    return p * __int_as_float((ni + 127) << 23);
}
__device__ __forceinline__ u32 pkbf(__nv_bfloat16 a, __nv_bfloat16 b) {
    return (u32)__bfloat16_as_ushort(a) | ((u32)__bfloat16_as_ushort(b) << 16);
}
__device__ __forceinline__ u32 pk_hi2(float x, float y) {
    return pkbf(__float2bfloat16(x), __float2bfloat16(y));
}
__device__ __forceinline__ u32 pk_lo2(float x, float y) {
    __nv_bfloat16 hx = __float2bfloat16(x), hy = __float2bfloat16(y);
    return pkbf(__float2bfloat16(x - __bfloat162float(hx)),
                __float2bfloat16(y - __bfloat162float(hy)));
}

// ---------------------------------------------------------------------------
// 1) Projections: relu(W[64x128]*pc[128x2048]+b).
//    theta,phi -> bf16 hi/lo [tn][64];  g -> fp32 [tn][64].
// ---------------------------------------------------------------------------
__global__ void __launch_bounds__(256)
proj_kernel(const float* __restrict__ pc,
            const float* __restrict__ tw, const float* __restrict__ tb,
            const float* __restrict__ pw, const float* __restrict__ pb,
            const float* __restrict__ gw, const float* __restrict__ gb)
{
    __shared__ float As[32 * 64];
    __shared__ float Bs[32 * 128];
    const int b = blockIdx.z, pj = blockIdx.y;
    const int n0 = blockIdx.x * 128;
    const float *W, *bi;
    if (pj == 0)      { W = tw; bi = tb; }
    else if (pj == 1) { W = pw; bi = pb; }
    else              { W = gw; bi = gb; }
    const float* pcb = pc + (size_t)b * CH * TN;
    const int tid = threadIdx.x;
    const int tx = tid & 15, ty = tid >> 4;

    u64 acc[4][4];
#pragma unroll
    for (int i = 0; i < 4; i++)
#pragma unroll
        for (int j = 0; j < 4; j++) acc[i][j] = 0ULL;

    for (int ct = 0; ct < 128; ct += 32) {
#pragma unroll
        for (int t = 0; t < 2; t++) {
            int f4 = tid + t * 256;
            int m = f4 >> 3, c4 = (f4 & 7) << 2;
            float4 w4 = *(const float4*)&W[m * 128 + ct + c4];
            As[(c4 + 0) * 64 + m] = w4.x;  As[(c4 + 1) * 64 + m] = w4.y;
            As[(c4 + 2) * 64 + m] = w4.z;  As[(c4 + 3) * 64 + m] = w4.w;
        }
#pragma unroll
        for (int t = 0; t < 4; t++) {
            int f4 = tid + t * 256;
            int cc = f4 >> 5, c4 = (f4 & 31) << 2;
            *(float4*)&Bs[cc * 128 + c4] =
                *(const float4*)&pcb[(size_t)(ct + cc) * TN + n0 + c4];
        }
        __syncthreads();
#pragma unroll 8
        for (int cc = 0; cc < 32; cc++) {
            float4 av = *(float4*)&As[cc * 64 + ty * 4];
            ulonglong2 b01 = *(ulonglong2*)&Bs[cc * 128 + tx * 8];
            ulonglong2 b23 = *(ulonglong2*)&Bs[cc * 128 + tx * 8 + 4];
            u64 aa[4] = { splat2(av.x), splat2(av.y), splat2(av.z), splat2(av.w) };
            u64 bb[4] = { b01.x, b01.y, b23.x, b23.y };
#pragma unroll
            for (int i = 0; i < 4; i++)
#pragma unroll
                for (int j = 0; j < 4; j++)
                    acc[i][j] = fma2_(aa[i], bb[j], acc[i][j]);
        }
        __syncthreads();
    }

    float v[4][8];
#pragma unroll
    for (int i = 0; i < 4; i++) {
#pragma unroll
        for (int j2 = 0; j2 < 4; j2++) upk2(acc[i][j2], v[i][2 * j2], v[i][2 * j2 + 1]);
        float bv = bi[ty * 4 + i];
#pragma unroll
        for (int j = 0; j < 8; j++) v[i][j] = fmaxf(v[i][j] + bv, 0.f);
    }
    if (pj < 2) {
        __nv_bfloat16* oh = (pj == 0 ? g_thhi : g_phhi) + (size_t)b * TN * MIDC;
        __nv_bfloat16* ol = (pj == 0 ? g_thlo : g_phlo) + (size_t)b * TN * MIDC;
#pragma unroll
        for (int j = 0; j < 8; j++) {
            int tn = n0 + tx * 8 + j;
            *(uint2*)&oh[(size_t)tn * MIDC + ty * 4] =
                make_uint2(pk_hi2(v[0][j], v[1][j]), pk_hi2(v[2][j], v[3][j]));
            *(uint2*)&ol[(size_t)tn * MIDC + ty * 4] =
                make_uint2(pk_lo2(v[0][j], v[1][j]), pk_lo2(v[2][j], v[3][j]));
        }
    } else {
        float* ob = g_g + (size_t)b * TN * MIDC;
#pragma unroll
        for (int j = 0; j < 8; j++)
            *(float4*)&ob[(size_t)(n0 + tx * 8 + j) * MIDC + ty * 4] =
                make_float4(v[0][j], v[1][j], v[2][j], v[3][j]);
    }
}

// ---------------------------------------------------------------------------
// 2) scores via warp-MMA bf16 3-pass + fused exp + register colsum.
//    Stores only E hi (bf16). smem: operands 64KB; staging/red overlay.
// ---------------------------------------------------------------------------
#define SC_SMEM 65536

__global__ void __launch_bounds__(256)
scores_kernel()
{
    extern __shared__ char smem[];
    const u32 sb = smem_u32(smem);
    const int b = blockIdx.z, qt = blockIdx.y, kt = blockIdx.x;
    const int q0 = qt * 128, k0 = kt * 128;
    const int tid = threadIdx.x, wid = tid >> 5, lane = tid & 31;
    const int wq = wid >> 1, wk = wid & 1;

    // load 4 operand tiles (128 rows x 64 bf16) swizzled
    {
        const __nv_bfloat16* s0 = g_thhi + (size_t)(b * TN + q0) * MIDC;
        const __nv_bfloat16* s1 = g_thlo + (size_t)(b * TN + q0) * MIDC;
        const __nv_bfloat16* s2 = g_phhi + (size_t)(b * TN + k0) * MIDC;
        const __nv_bfloat16* s3 = g_phlo + (size_t)(b * TN + k0) * MIDC;
        const __nv_bfloat16* srcs[4] = { s0, s1, s2, s3 };
#pragma unroll
        for (int it = 0; it < 16; it++) {
            int idx = tid + it * 256;            // 0..4095 16B units
            int mat = idx >> 10, row = (idx >> 3) & 127, u = idx & 7;
            uint4 v = *(const uint4*)(srcs[mat] + (size_t)row * MIDC + u * 8);
            *(uint4*)(smem + mat * 16384 + SWZ128(row * 128 + u * 16)) = v;
        }
    }
    __syncthreads();

    float acc[2][8][4];
#pragma unroll
    for (int i = 0; i < 2; i++)
#pragma unroll
        for (int j = 0; j < 8; j++)
#pragma unroll
            for (int r = 0; r < 4; r++) acc[i][j][r] = 0.f;

    const u32 baseA[2] = { sb, sb + 16384 };
    const u32 baseB[2] = { sb + 32768, sb + 49152 };
    const int pa[3] = { 0, 0, 1 }, pbx[3] = { 0, 1, 0 };
    const int arow = wq * 32 + (lane & 15);
    const int acolx = (lane >> 4) << 4;
    const int brow = wk * 64 + (lane & 7) + ((lane >> 4) << 3);
    const int bcolx = ((lane >> 3) & 1) << 4;

#pragma unroll
    for (int p = 0; p < 3; p++) {
        u32 bA = baseA[pa[p]], bB = baseB[pbx[p]];
#pragma unroll
        for (int ks = 0; ks < 4; ks++) {
            int kb = ks * 32;
            u32 a0[4], a1[4];
            ldsm4(a0, bA + SWZ128((arow) * 128 + kb + acolx));
            ldsm4(a1, bA + SWZ128((arow + 16) * 128 + kb + acolx));
#pragma unroll
            for (int jp = 0; jp < 4; jp++) {
                u32 bb[4];
                ldsm4(bb, bB + SWZ128((brow + jp * 16) * 128 + kb + bcolx));
                mma16816(acc[0][2 * jp],     a0, bb[0], bb[1]);
                mma16816(acc[0][2 * jp + 1], a0, bb[2], bb[3]);
                mma16816(acc[1][2 * jp],     a1, bb[0], bb[1]);
                mma16816(acc[1][2 * jp + 1], a1, bb[2], bb[3]);
            }
        }
    }
    __syncthreads();                             // operands dead

    // exp in registers (fp32), stage E hi, per-column fp32 partial sums
    float* red = (float*)(smem + 33792);         // [4 wq][128 k]
#pragma unroll
    for (int i = 0; i < 2; i++)
#pragma unroll
        for (int j = 0; j < 8; j++)
#pragma unroll
            for (int r = 0; r < 4; r++) acc[i][j][r] = fexp(acc[i][j][r]);

#pragma unroll
    for (int i = 0; i < 2; i++) {
        int qr = wq * 32 + i * 16 + (lane >> 2);
#pragma unroll
        for (int j = 0; j < 8; j++) {
            int kc = wk * 64 + j * 8 + 2 * (lane & 3);
            *(u32*)(smem + qr * 264 + kc * 2)       = pk_hi2(acc[i][j][0], acc[i][j][1]);
            *(u32*)(smem + (qr + 8) * 264 + kc * 2) = pk_hi2(acc[i][j][2], acc[i][j][3]);
        }
    }
#pragma unroll
    for (int j = 0; j < 8; j++) {
        float c0 = (acc[0][j][0] + acc[0][j][2]) + (acc[1][j][0] + acc[1][j][2]);
        float c1 = (acc[0][j][1] + acc[0][j][3]) + (acc[1][j][1] + acc[1][j][3]);
#pragma unroll
        for (int off = 4; off < 32; off <<= 1) {
            c0 += __shfl_xor_sync(0xFFFFFFFFu, c0, off);
            c1 += __shfl_xor_sync(0xFFFFFFFFu, c1, off);
        }
        if (lane < 4) {
            int kc = wk * 64 + j * 8 + 2 * lane;
            red[wq * 128 + kc]     = c0;
            red[wq * 128 + kc + 1] = c1;
        }
    }
    __syncthreads();

    if (tid < 128) {
        float z = (red[tid] + red[128 + tid]) + (red[256 + tid] + red[384 + tid]);
        g_Zp[(qt * BATCH + b) * TN + k0 + tid] = z;
    }

    // coalesced copy-out of E hi (128 rows x 256B)
    for (int row = wid; row < 128; row += 8) {
        uint2 v = *(const uint2*)(smem + row * 264 + lane * 8);
        *(uint2*)&g_Ehi[(size_t)(b * TN + q0 + row) * TN + k0 + lane * 4] = v;
    }
}

// ---------------------------------------------------------------------------
// 3) scalegT (invZ fused): gsT hi/lo [m][k] = bf16 split of g[k][m]/Z[k]
// ---------------------------------------------------------------------------
__global__ void __launch_bounds__(256)
scalegT_kernel()
{
    __shared__ float s[64][65];
    __shared__ float siz[64];
    const int k0 = blockIdx.x * 64, b = blockIdx.y;
    const int tid = threadIdx.x;
    if (tid < 64) {
        int idx = b * TN + k0 + tid;
        float z = 0.f;
#pragma unroll
        for (int t = 0; t < 16; t++) z += g_Zp[t * 16384 + idx];
        siz[tid] = 1.0f / z;
    }
    __syncthreads();
#pragma unroll
    for (int t = 0; t < 4; t++) {
        int f4 = tid + t * 256;
        int row = f4 >> 4, c4 = (f4 & 15) << 2;
        float iz = siz[row];
        float4 v = *(const float4*)&g_g[(size_t)(b * TN + k0 + row) * MIDC + c4];
        s[row][c4 + 0] = v.x * iz;  s[row][c4 + 1] = v.y * iz;
        s[row][c4 + 2] = v.z * iz;  s[row][c4 + 3] = v.w * iz;
    }
    __syncthreads();
    int m = tid >> 2, kk0 = (tid & 3) << 4;
    u32 hw[8], lw[8];
#pragma unroll
    for (int j = 0; j < 8; j++) {
        float v0 = s[kk0 + 2 * j][m], v1 = s[kk0 + 2 * j + 1][m];
        hw[j] = pk_hi2(v0, v1);
        lw[j] = pk_lo2(v0, v1);
    }
    size_t doff = (size_t)(b * MIDC + m) * TN + k0 + kk0;
    *(uint4*)&g_gsThi[doff]     = make_uint4(hw[0], hw[1], hw[2], hw[3]);
    *(uint4*)&g_gsThi[doff + 8] = make_uint4(hw[4], hw[5], hw[6], hw[7]);
    *(uint4*)&g_gsTlo[doff]     = make_uint4(lw[0], lw[1], lw[2], lw[3]);
    *(uint4*)&g_gsTlo[doff + 8] = make_uint4(lw[4], lw[5], lw[6], lw[7]);
}

// ---------------------------------------------------------------------------
// 4) attn_y: y[q][m] = sum_k Ehi[q][k] * gs[k][m], 2 passes (gs hi + gs lo).
//    q-tile 64 -> 256 blocks (no grid starvation). Static smem 24.6KB.
// smem: A Ehi [64][64] swz @0 (8KB); B gshi @8192, gslo @16384 (8KB each);
//       epilogue ys[64][65] fp32 overlays 0..16640.
// ---------------------------------------------------------------------------
__global__ void __launch_bounds__(256)
attn_y_kernel()
{
    __shared__ __align__(16) char smem[24576];
    const u32 sb = smem_u32(smem);
    const int qt = blockIdx.x, b = blockIdx.y;
    const int q0 = qt * 64;
    const int tid = threadIdx.x, wid = tid >> 5, lane = tid & 31;
    const int wq = wid >> 1, wm = wid & 1;

    float acc[4][4];
#pragma unroll
    for (int j = 0; j < 4; j++)
#pragma unroll
        for (int r = 0; r < 4; r++) acc[j][r] = 0.f;

    const int arow = wq * 16 + (lane & 15);
    const int acolx = (lane >> 4) << 4;
    const int brow = wm * 32 + (lane & 7) + ((lane >> 4) << 3);
    const int bcolx = ((lane >> 3) & 1) << 4;

    for (int ch = 0; ch < 32; ch++) {
        const int kc = ch * 64;
#pragma unroll
        for (int it = 0; it < 2; it++) {         // Ehi [64 q][64 k]
            int idx = tid + it * 256;            // 0..511 16B units
            int row = idx >> 3, u = idx & 7;
            *(uint4*)(smem + SWZ128(row * 128 + u * 16)) =
                *(const uint4*)&g_Ehi[(size_t)(b * TN + q0 + row) * TN + kc + u * 8];
        }
#pragma unroll
        for (int it = 0; it < 4; it++) {         // gsT hi/lo [64 m][64 k]
            int idx = tid + it * 256;            // 0..1023
            int mat = idx >> 9, row = (idx >> 3) & 63, u = idx & 7;
            const __nv_bfloat16* src = (mat ? g_gsTlo : g_gsThi)
                + (size_t)(b * MIDC + row) * TN + kc + u * 8;
            *(uint4*)(smem + 8192 + mat * 8192 + SWZ128(row * 128 + u * 16)) =
                *(const uint4*)src;
        }
        __syncthreads();
#pragma unroll
        for (int p = 0; p < 2; p++) {            // pass 0: gs hi, pass 1: gs lo
            u32 bB = sb + 8192 + p * 8192;
#pragma unroll
            for (int ks = 0; ks < 4; ks++) {
                int kb = ks * 32;
                u32 a0[4];
                ldsm4(a0, sb + SWZ128(arow * 128 + kb + acolx));
#pragma unroll
                for (int jp = 0; jp < 2; jp++) {
                    u32 bb[4];
                    ldsm4(bb, bB + SWZ128((brow + jp * 16) * 128 + kb + bcolx));
                    mma16816(acc[2 * jp],     a0, bb[0], bb[1]);
                    mma16816(acc[2 * jp + 1], a0, bb[2], bb[3]);
                }
            }
        }
        __syncthreads();
    }

    // epilogue: stage D[64 q][64 m] fp32 (stride 65), write y^T[m][q]
    float* ys = (float*)smem;
    {
        int qr = wq * 16 + (lane >> 2);
#pragma unroll
        for (int j = 0; j < 4; j++) {
            int mc = wm * 32 + j * 8 + 2 * (lane & 3);
            ys[qr * 65 + mc]           = acc[j][0];
            ys[qr * 65 + mc + 1]       = acc[j][1];
            ys[(qr + 8) * 65 + mc]     = acc[j][2];
            ys[(qr + 8) * 65 + mc + 1] = acc[j][3];
        }
    }
    __syncthreads();
    for (int m = wid; m < 64; m += 8) {
        float2 f = make_float2(ys[(lane * 2 + 0) * 65 + m],
                               ys[(lane * 2 + 1) * 65 + m]);
        *(float2*)&g_yT[(size_t)(b * MIDC + m) * TN + q0 + lane * 2] = f;
    }
}

// ---------------------------------------------------------------------------
// 5) refine (FFMA2): refined[q][o] = relu(sum_m yT[m][q]*rw[o][m] + rb[o])
// ---------------------------------------------------------------------------
__global__ void __launch_bounds__(256)
refine_kernel(const float* __restrict__ RW, const float* __restrict__ RB)
{
    __shared__ float As[32 * 128];
    __shared__ float Bs[32 * 128];
    const int b = blockIdx.z;
    const int q0 = blockIdx.x * 128;
    const float* Yb = g_yT + (size_t)b * MIDC * TN;
    const int tid = threadIdx.x;
    const int tx = tid & 15, ty = tid >> 4;

    u64 acc[8][4];
#pragma unroll
    for (int i = 0; i < 8; i++)
#pragma unroll
        for (int j = 0; j < 4; j++) acc[i][j] = 0ULL;

    for (int mt = 0; mt < MIDC; mt += 32) {
#pragma unroll
        for (int t = 0; t < 4; t++) {
            int f4 = tid + t * 256;
            int mm = f4 >> 5, c4 = (f4 & 31) << 2;
            *(float4*)&As[mm * 128 + c4] =
                *(const float4*)&Yb[(size_t)(mt + mm) * TN + q0 + c4];
        }
#pragma unroll
        for (int t = 0; t < 4; t++) {
            int f4 = tid + t * 256;
            int o = f4 >> 3, c4 = (f4 & 7) << 2;
            float4 w4 = *(const float4*)&RW[o * MIDC + mt + c4];
            Bs[(c4 + 0) * 128 + o] = w4.x;  Bs[(c4 + 1) * 128 + o] = w4.y;
            Bs[(c4 + 2) * 128 + o] = w4.z;  Bs[(c4 + 3) * 128 + o] = w4.w;
        }
        __syncthreads();
#pragma unroll 8
        for (int mm = 0; mm < 32; mm++) {
            float4 a0 = *(float4*)&As[mm * 128 + ty * 8];
            float4 a1 = *(float4*)&As[mm * 128 + ty * 8 + 4];
            ulonglong2 b01 = *(ulonglong2*)&Bs[mm * 128 + tx * 8];
            ulonglong2 b23 = *(ulonglong2*)&Bs[mm * 128 + tx * 8 + 4];
            u64 aa[8] = { splat2(a0.x), splat2(a0.y), splat2(a0.z), splat2(a0.w),
                          splat2(a1.x), splat2(a1.y), splat2(a1.z), splat2(a1.w) };
            u64 bb[4] = { b01.x, b01.y, b23.x, b23.y };
#pragma unroll
            for (int i = 0; i < 8; i++)
#pragma unroll
                for (int j = 0; j < 4; j++)
                    acc[i][j] = fma2_(aa[i], bb[j], acc[i][j]);
        }
        __syncthreads();
    }

    float* Rb = g_ref + (size_t)b * TN * OUTC;
    float rbv[8];
#pragma unroll
    for (int j = 0; j < 8; j++) rbv[j] = RB[tx * 8 + j];
#pragma unroll
    for (int i = 0; i < 8; i++) {
        float v[8];
#pragma unroll
        for (int j2 = 0; j2 < 4; j2++) upk2(acc[i][j2], v[2 * j2], v[2 * j2 + 1]);
#pragma unroll
        for (int j = 0; j < 8; j++) v[j] = fmaxf(v[j] + rbv[j], 0.f);
        size_t row = (size_t)(q0 + ty * 8 + i) * OUTC + tx * 8;
        *(float4*)&Rb[row]     = make_float4(v[0], v[1], v[2], v[3]);
        *(float4*)&Rb[row + 4] = make_float4(v[4], v[5], v[6], v[7]);
    }
}

// ---------------------------------------------------------------------------
// 6) out[b,c,t,n] = refined[b][q][o] + pc, q=(n&15)*128+c, o=t*32+(n>>4)
//    Vectorized x4 along n (n%16 in {0,4,8,12} keeps o constant).
// ---------------------------------------------------------------------------
__global__ void __launch_bounds__(256)
scatter_kernel(const float* __restrict__ pc, float* __restrict__ out)
{
    int i4 = blockIdx.x * 256 + threadIdx.x;     // 524288 float4 tasks
    int idx = i4 << 2;
    int b = idx >> 18;
    int r = idx & 262143;
    int c = r >> 11;
    int t = (r >> 9) & 3;
    int n = r & 511;
    int o = (t << 5) + (n >> 4);
    int qb = ((n & 15) << 7) + c;
    const float* Rb = g_ref + ((size_t)b << 18) + o;
    float4 p = *(const float4*)&pc[idx];
    float4 v;
    v.x = Rb[(qb       ) << 7] + p.x;
    v.y = Rb[(qb +  128) << 7] + p.y;
    v.z = Rb[(qb +  256) << 7] + p.z;
    v.w = Rb[(qb +  384) << 7] + p.w;
    *(float4*)&out[idx] = v;
}

// ---------------------------------------------------------------------------
// Host launcher
// ---------------------------------------------------------------------------
extern "C" void kernel_launch(void* const* d_in, const int* in_sizes, int n_in,
                              void* d_out, int out_size)
{
    const float* pc = (const float*)d_in[0];
    const float* tw = (const float*)d_in[1];
    const float* tb = (const float*)d_in[2];
    const float* pw = (const float*)d_in[3];
    const float* pb = (const float*)d_in[4];
    const float* gw = (const float*)d_in[5];
    const float* gb = (const float*)d_in[6];
    const float* rw = (const float*)d_in[7];
    const float* rb = (const float*)d_in[8];
    float* out = (float*)d_out;

    cudaFuncSetAttribute(scores_kernel,
                         cudaFuncAttributeMaxDynamicSharedMemorySize, SC_SMEM);

    proj_kernel   <<<dim3(16, 3, BATCH), 256>>>(pc, tw, tb, pw, pb, gw, gb);
    scores_kernel <<<dim3(16, 16, BATCH), 256, SC_SMEM>>>();
    scalegT_kernel<<<dim3(32, BATCH), 256>>>();
    attn_y_kernel <<<dim3(32, BATCH), 256>>>();
    refine_kernel <<<dim3(16, 1, BATCH), 256>>>(rw, rb);
    scatter_kernel<<<2048, 256>>>(pc, out);
}